// round 3
// baseline (speedup 1.0000x reference)
#include <cuda_runtime.h>
#include <cuda_bf16.h>
#include <math.h>

// Problem constants
constexpr int kT = 386;       // LSTM positions (SENT_LEN + 2)
constexpr int kH = 512;       // hidden dim
constexpr int kG = 2048;      // 4*H gates
constexpr int kE = 1024;      // enc dim (2H)
constexpr int kS = 73920;     // number of spans = 385*384/2

// ---------------- scratch (device globals; no allocation) ----------------
__device__ float g_x [kT * kH];           // embedded input [T,512]
__device__ float g_gx[2 * kT * kG];       // x@Wih^T + b per direction [2][T][2048]
__device__ float g_h [2 * kT * kH];       // fwd/bwd hidden states [2][T][512]
__device__ float g_A1[2 * kT * kE];       // fwd@W1_top / bwd@W1_bot  [2][T][1024]
__device__ float g_Av[2 * kT * kE];       // fwd@V1_top / bwd@V1_bot  [2][T][1024]
__device__ int   g_L[kS];
__device__ int   g_R[kS];
__device__ unsigned g_bar[2];             // per-direction step barrier

// ---------------- init: embeddings gather + span index tables + barrier reset ----
__global__ void init_kernel(const int* __restrict__ tag_ids,
                            const int* __restrict__ word_ids,
                            const float* __restrict__ tag_emb,
                            const float* __restrict__ word_emb)
{
    int b = blockIdx.x, tid = threadIdx.x;
    if (b == 0 && tid < 2) g_bar[tid] = 0u;
    if (b < kT) {
        int t = b;
        int tg = tag_ids[t], wd = word_ids[t];
        for (int i = tid; i < kH; i += 256) {
            float v = (i < 128) ? tag_emb[tg * 128 + i] : word_emb[wd * 384 + (i - 128)];
            g_x[t * kH + i] = v;
        }
    } else {
        int s = (b - kT) * 256 + tid;
        if (s < kS) {
            // invert triangular index: off(l) = (769*l - l*l)/2
            int l = (int)((769.0 - sqrt((double)(591361 - 8 * s))) * 0.5);
            if (l < 0) l = 0; if (l > 383) l = 383;
            while (l < 383 && (769 * (l + 1) - (l + 1) * (l + 1)) / 2 <= s) l++;
            while (l > 0 && (769 * l - l * l) / 2 > s) l--;
            int off = (769 * l - l * l) / 2;
            g_L[s] = l;
            g_R[s] = l + 1 + (s - off);
        }
    }
}

// ---------------- gx GEMM: gx[dir] = x @ Wih^T + b   (NT layout) ----------------
// M=386, N=2048, K=512. A=[M,K] row-major, B=[N,K] row-major.
__global__ __launch_bounds__(256) void gx_gemm(const float* __restrict__ Wf,
                                               const float* __restrict__ bfv,
                                               const float* __restrict__ Wb,
                                               const float* __restrict__ bbv)
{
    int dir = blockIdx.z;
    const float* B    = dir ? Wb : Wf;
    const float* bias = dir ? bbv : bfv;
    const float* A = g_x;
    float* C = g_gx + (size_t)dir * kT * kG;

    int tid = threadIdx.x;
    int m0 = blockIdx.x * 64, n0 = blockIdx.y * 64;
    __shared__ __align__(16) float As[16][68];
    __shared__ __align__(16) float Bs[16][68];
    float acc[4][4] = {};
    int tx = tid & 15, ty = tid >> 4;

    for (int k0 = 0; k0 < kH; k0 += 16) {
        int mr = tid >> 2, kq = (tid & 3) * 4;
        int gm = m0 + mr;
        float4 va = (gm < kT) ? *(const float4*)&A[(size_t)gm * kH + k0 + kq]
                              : make_float4(0.f, 0.f, 0.f, 0.f);
        As[kq + 0][mr] = va.x; As[kq + 1][mr] = va.y;
        As[kq + 2][mr] = va.z; As[kq + 3][mr] = va.w;
        float4 vb = *(const float4*)&B[(size_t)(n0 + mr) * kH + k0 + kq];
        Bs[kq + 0][mr] = vb.x; Bs[kq + 1][mr] = vb.y;
        Bs[kq + 2][mr] = vb.z; Bs[kq + 3][mr] = vb.w;
        __syncthreads();
        #pragma unroll
        for (int k = 0; k < 16; k++) {
            float4 a = *(const float4*)&As[k][ty * 4];
            float4 bv = *(const float4*)&Bs[k][tx * 4];
            float av[4] = {a.x, a.y, a.z, a.w};
            float bw[4] = {bv.x, bv.y, bv.z, bv.w};
            #pragma unroll
            for (int i = 0; i < 4; i++)
                #pragma unroll
                for (int j = 0; j < 4; j++)
                    acc[i][j] = fmaf(av[i], bw[j], acc[i][j]);
        }
        __syncthreads();
    }
    #pragma unroll
    for (int i = 0; i < 4; i++) {
        int gm = m0 + ty * 4 + i;
        if (gm < kT) {
            #pragma unroll
            for (int j = 0; j < 4; j++) {
                int n = n0 + tx * 4 + j;
                C[(size_t)gm * kG + n] = acc[i][j] + bias[n];
            }
        }
    }
}

// ---------------- persistent bidirectional LSTM ----------------
// 64 CTAs: CTAs [0,32) = forward, [32,64) = backward. Each CTA owns 16 hidden
// units (64 gate rows); Whh slice lives in registers (16 float4 per thread).
// Per-direction monotonic barrier; release+acquire fences around it.
__global__ __launch_bounds__(512, 1) void lstm_kernel(const float* __restrict__ Wfhh,
                                                      const float* __restrict__ Wbhh)
{
    int tid = threadIdx.x;
    int dir = blockIdx.x >> 5;
    int cta = blockIdx.x & 31;
    int lr  = tid >> 3;      // local gate row 0..63
    int sl  = tid & 7;       // slice within row
    int gate = lr >> 4, u = lr & 15;
    int ug  = cta * 16 + u;
    int row = gate * kH + ug;

    const float* W = (dir ? Wbhh : Wfhh) + (size_t)row * kH;
    float4 w4[16];
    int koff[16];
    #pragma unroll
    for (int m = 0; m < 16; m++) {
        int ko = sl * 64 + ((4 * m + 4 * sl) & 63);   // bank-rotated k offset
        koff[m] = ko;
        w4[m] = *(const float4*)&W[ko];
    }

    __shared__ __align__(16) float sh_h[kH];
    __shared__ float sh_g[64];
    __shared__ float sh_c[16];
    if (tid < 16) sh_c[tid] = 0.f;

    float* hbase = g_h + (size_t)dir * kT * kH;
    const float* gxbase = g_gx + (size_t)dir * kT * kG;
    unsigned* bar = &g_bar[dir];

    for (int step = 0; step < kT; step++) {
        int t = dir ? (kT - 1 - step) : step;
        if (step == 0) {
            sh_h[tid] = 0.f;
        } else {
            int tp = dir ? t + 1 : t - 1;
            sh_h[tid] = __ldcg(&hbase[(size_t)tp * kH + tid]);
        }
        __syncthreads();

        float acc = 0.f;
        #pragma unroll
        for (int m = 0; m < 16; m++) {
            float4 h4 = *(const float4*)&sh_h[koff[m]];
            acc = fmaf(w4[m].x, h4.x, acc);
            acc = fmaf(w4[m].y, h4.y, acc);
            acc = fmaf(w4[m].z, h4.z, acc);
            acc = fmaf(w4[m].w, h4.w, acc);
        }
        acc += __shfl_down_sync(0xffffffffu, acc, 4, 8);
        acc += __shfl_down_sync(0xffffffffu, acc, 2, 8);
        acc += __shfl_down_sync(0xffffffffu, acc, 1, 8);
        if (sl == 0) sh_g[lr] = acc;
        __syncthreads();

        if (tid < 16) {
            const float* gx = gxbase + (size_t)t * kG;
            int ugl = cta * 16 + tid;
            float gi = gx[ugl]            + sh_g[tid];
            float gf = gx[kH + ugl]       + sh_g[16 + tid];
            float gg = gx[2 * kH + ugl]   + sh_g[32 + tid];
            float go = gx[3 * kH + ugl]   + sh_g[48 + tid];
            float si = 1.f / (1.f + expf(-gi));
            float sf = 1.f / (1.f + expf(-gf));
            float so = 1.f / (1.f + expf(-go));
            float c = sf * sh_c[tid] + si * tanhf(gg);
            sh_c[tid] = c;
            float h = so * tanhf(c);
            __stcg(&hbase[(size_t)t * kH + ugl], h);
        }
        __syncthreads();
        if (tid == 0) {
            __threadfence();                               // release h writes
            unsigned tgt = (unsigned)(step + 1) * 32u;
            atomicAdd(bar, 1u);
            volatile unsigned* bp = bar;
            while (*bp < tgt) { }
            __threadfence();                               // acquire peers' h writes
        }
        __syncthreads();
    }
}

// ---------------- A-table GEMMs: A[dir] = h[dir] @ Wtab[dir_half]  (NN) --------
// M=386, N=1024, K=512. B=[K,N] row-major (n contiguous).
__global__ __launch_bounds__(256) void pre_gemm(const float* __restrict__ W1,
                                                const float* __restrict__ V1)
{
    int dir = blockIdx.z & 1, tab = blockIdx.z >> 1;
    const float* A = g_h + (size_t)dir * kT * kH;
    const float* B = (tab ? V1 : W1) + (size_t)dir * kH * kE;
    float* C = (tab ? g_Av : g_A1) + (size_t)dir * kT * kE;

    int tid = threadIdx.x;
    int m0 = blockIdx.x * 64, n0 = blockIdx.y * 64;
    __shared__ __align__(16) float As[16][68];
    __shared__ __align__(16) float Bs[16][68];
    float acc[4][4] = {};
    int tx = tid & 15, ty = tid >> 4;

    for (int k0 = 0; k0 < kH; k0 += 16) {
        {
            int mr = tid >> 2, kq = (tid & 3) * 4;
            int gm = m0 + mr;
            float4 va = (gm < kT) ? *(const float4*)&A[(size_t)gm * kH + k0 + kq]
                                  : make_float4(0.f, 0.f, 0.f, 0.f);
            As[kq + 0][mr] = va.x; As[kq + 1][mr] = va.y;
            As[kq + 2][mr] = va.z; As[kq + 3][mr] = va.w;
        }
        {
            int kr = tid >> 4, nq = (tid & 15) * 4;
            float4 vb = *(const float4*)&B[(size_t)(k0 + kr) * kE + n0 + nq];
            *(float4*)&Bs[kr][nq] = vb;
        }
        __syncthreads();
        #pragma unroll
        for (int k = 0; k < 16; k++) {
            float4 a = *(const float4*)&As[k][ty * 4];
            float4 bv = *(const float4*)&Bs[k][tx * 4];
            float av[4] = {a.x, a.y, a.z, a.w};
            float bw[4] = {bv.x, bv.y, bv.z, bv.w};
            #pragma unroll
            for (int i = 0; i < 4; i++)
                #pragma unroll
                for (int j = 0; j < 4; j++)
                    acc[i][j] = fmaf(av[i], bw[j], acc[i][j]);
        }
        __syncthreads();
    }
    #pragma unroll
    for (int i = 0; i < 4; i++) {
        int gm = m0 + ty * 4 + i;
        if (gm < kT) {
            #pragma unroll
            for (int j = 0; j < 4; j++)
                C[(size_t)gm * kE + n0 + tx * 4 + j] = acc[i][j];
        }
    }
}

// ---------------- fused span kernel ----------------
// Tile: 64 spans x 128 labels, K=1024 in chunks of 32. h1 built on the fly from
// A-tables (relu'd), split score (V path) accumulated inline during the build.
__global__ __launch_bounds__(256) void span_kernel(const float* __restrict__ W2,
                                                   const float* __restrict__ b1,
                                                   const float* __restrict__ b2,
                                                   const float* __restrict__ V2,
                                                   const float* __restrict__ c1,
                                                   const float* __restrict__ c2,
                                                   float* __restrict__ out)
{
    __shared__ __align__(16) float h1s[64][33];
    __shared__ __align__(16) float w2s[32][128];
    __shared__ int sL[64], sR[64];
    __shared__ float ssplit[64];

    int tid = threadIdx.x;
    int s0 = blockIdx.x * 64;
    if (tid < 64) {
        int s = s0 + tid;
        if (s < kS) { sL[tid] = g_L[s]; sR[tid] = g_R[s]; }
        else        { sL[tid] = 0;      sR[tid] = 1;      }
        ssplit[tid] = 0.f;
    }
    __syncthreads();

    const float* A1f = g_A1;
    const float* A1b = g_A1 + (size_t)kT * kE;
    const float* Avf = g_Av;
    const float* Avb = g_Av + (size_t)kT * kE;

    float acc[4][8] = {};
    float spl[8] = {};
    int lane_k = tid & 31;
    int mwarp  = tid >> 5;
    int tx = tid & 15, ty = tid >> 4;

    for (int kc = 0; kc < 32; kc++) {
        int k0 = kc * 32;
        // load W2 chunk [32][128]
        #pragma unroll
        for (int i = 0; i < 4; i++) {
            int e = tid + 256 * i;             // float4 index
            int kk = e >> 5;
            int nq = (e & 31) * 4;
            *(float4*)&w2s[kk][nq] = *(const float4*)&W2[(size_t)(k0 + kk) * 128 + nq];
        }
        int kg = k0 + lane_k;
        float b1v = b1[kg], c1v = c1[kg], v2v = V2[kg];
        // build h1 chunk + split partials (coalesced along k)
        #pragma unroll
        for (int i = 0; i < 8; i++) {
            int m = mwarp + 8 * i;
            int l = sL[m], r = sR[m];
            size_t rr = (size_t)r * kE + kg, ll = (size_t)l * kE + kg;
            size_t l1 = (size_t)(l + 1) * kE + kg, r1 = (size_t)(r + 1) * kE + kg;
            float hl = A1f[rr] - A1f[ll] + A1b[l1] - A1b[r1] + b1v;
            h1s[m][lane_k] = fmaxf(hl, 0.f);
            float hv = Avf[rr] - Avf[ll] + Avb[l1] - Avb[r1] + c1v;
            spl[i] = fmaf(fmaxf(hv, 0.f), v2v, spl[i]);
        }
        __syncthreads();
        // GEMM: 64x128 += h1(64x32) * w2(32x128)
        #pragma unroll
        for (int k = 0; k < 32; k++) {
            float4 wA = *(const float4*)&w2s[k][tx * 8];
            float4 wB = *(const float4*)&w2s[k][tx * 8 + 4];
            #pragma unroll
            for (int i = 0; i < 4; i++) {
                float a = h1s[ty * 4 + i][k];
                acc[i][0] = fmaf(a, wA.x, acc[i][0]);
                acc[i][1] = fmaf(a, wA.y, acc[i][1]);
                acc[i][2] = fmaf(a, wA.z, acc[i][2]);
                acc[i][3] = fmaf(a, wA.w, acc[i][3]);
                acc[i][4] = fmaf(a, wB.x, acc[i][4]);
                acc[i][5] = fmaf(a, wB.y, acc[i][5]);
                acc[i][6] = fmaf(a, wB.z, acc[i][6]);
                acc[i][7] = fmaf(a, wB.w, acc[i][7]);
            }
        }
        __syncthreads();
    }

    // reduce split partials (each warp owns spans m with m%8 == warp id)
    #pragma unroll
    for (int i = 0; i < 8; i++) {
        float v = spl[i];
        v += __shfl_down_sync(0xffffffffu, v, 16);
        v += __shfl_down_sync(0xffffffffu, v, 8);
        v += __shfl_down_sync(0xffffffffu, v, 4);
        v += __shfl_down_sync(0xffffffffu, v, 2);
        v += __shfl_down_sync(0xffffffffu, v, 1);
        if (lane_k == 0) ssplit[mwarp + 8 * i] = v;
    }
    __syncthreads();

    float c2v = c2[0];
    #pragma unroll
    for (int i = 0; i < 4; i++) {
        int s = s0 + ty * 4 + i;
        if (s < kS) {
            float* po = out + (size_t)s * 129;
            #pragma unroll
            for (int j = 0; j < 8; j++) {
                int n = tx * 8 + j;
                po[n] = acc[i][j] + b2[n];
            }
            if (tx == 0) po[128] = ssplit[ty * 4 + i] + c2v;
        }
    }
}

// ---------------- launch ----------------
extern "C" void kernel_launch(void* const* d_in, const int* in_sizes, int n_in,
                              void* d_out, int out_size)
{
    const int*   tag_ids  = (const int*)  d_in[0];
    const int*   word_ids = (const int*)  d_in[1];
    const float* tag_emb  = (const float*)d_in[2];
    const float* word_emb = (const float*)d_in[3];
    const float* Wf_ih    = (const float*)d_in[4];
    const float* Wf_hh    = (const float*)d_in[5];
    const float* bf       = (const float*)d_in[6];
    const float* Wb_ih    = (const float*)d_in[7];
    const float* Wb_hh    = (const float*)d_in[8];
    const float* bb       = (const float*)d_in[9];
    const float* W1       = (const float*)d_in[10];
    const float* b1       = (const float*)d_in[11];
    const float* W2       = (const float*)d_in[12];
    const float* b2       = (const float*)d_in[13];
    const float* V1       = (const float*)d_in[14];
    const float* c1       = (const float*)d_in[15];
    const float* V2       = (const float*)d_in[16];
    const float* c2       = (const float*)d_in[17];
    float* out = (float*)d_out;

    init_kernel<<<kT + (kS + 255) / 256, 256>>>(tag_ids, word_ids, tag_emb, word_emb);
    gx_gemm<<<dim3((kT + 63) / 64, kG / 64, 2), 256>>>(Wf_ih, bf, Wb_ih, bb);
    lstm_kernel<<<64, 512>>>(Wf_hh, Wb_hh);
    pre_gemm<<<dim3((kT + 63) / 64, kE / 64, 4), 256>>>(W1, V1);
    span_kernel<<<(kS + 63) / 64, 256>>>(W2, b1, b2, V2, c1, c2, out);
}

// round 4
// speedup vs baseline: 1.1535x; 1.1535x over previous
#include <cuda_runtime.h>
#include <cuda_bf16.h>
#include <math.h>

// Problem constants
constexpr int kT = 386;       // LSTM positions (SENT_LEN + 2)
constexpr int kH = 512;       // hidden dim
constexpr int kG = 2048;      // 4*H gates
constexpr int kE = 1024;      // enc dim (2H)
constexpr int kS = 73920;     // number of spans = 385*384/2

// ---------------- scratch (device globals; no allocation) ----------------
__device__ float g_x [kT * kH];           // embedded input [T,512]
__device__ float g_gx[2 * kT * kG];       // x@Wih^T + b per direction [2][T][2048]
__device__ float g_h [2 * kT * kH];       // fwd/bwd hidden states [2][T][512]
__device__ float g_A1[2 * kT * kE];       // fwd@W1_top / bwd@W1_bot  [2][T][1024]
__device__ float g_Av[2 * kT * kE];       // fwd@V1_top / bwd@V1_bot  [2][T][1024]
__device__ int   g_L[kS];
__device__ int   g_R[kS];
__device__ unsigned g_bar[64];            // per-direction barrier, 128B apart (idx 0, 32)

// ---------------- fast math helpers ----------------
__device__ __forceinline__ float fast_ex2(float x) {
    float r; asm("ex2.approx.ftz.f32 %0, %1;" : "=f"(r) : "f"(x)); return r;
}
__device__ __forceinline__ float fast_rcp(float x) {
    float r; asm("rcp.approx.ftz.f32 %0, %1;" : "=f"(r) : "f"(x)); return r;
}
__device__ __forceinline__ float fsig(float x) {
    return fast_rcp(1.f + fast_ex2(-1.44269504f * x));
}
__device__ __forceinline__ float ftanh(float x) {
    return fmaf(2.f, fsig(2.f * x), -1.f);
}

// ---------------- init: embeddings gather + span index tables + barrier reset ----
__global__ void init_kernel(const int* __restrict__ tag_ids,
                            const int* __restrict__ word_ids,
                            const float* __restrict__ tag_emb,
                            const float* __restrict__ word_emb)
{
    int b = blockIdx.x, tid = threadIdx.x;
    if (b == 0 && tid < 2) g_bar[tid * 32] = 0u;
    if (b < kT) {
        int t = b;
        int tg = tag_ids[t], wd = word_ids[t];
        for (int i = tid; i < kH; i += 256) {
            float v = (i < 128) ? tag_emb[tg * 128 + i] : word_emb[wd * 384 + (i - 128)];
            g_x[t * kH + i] = v;
        }
    } else {
        int s = (b - kT) * 256 + tid;
        if (s < kS) {
            // invert triangular index: off(l) = (769*l - l*l)/2
            int l = (int)((769.0 - sqrt((double)(591361 - 8 * s))) * 0.5);
            if (l < 0) l = 0; if (l > 383) l = 383;
            while (l < 383 && (769 * (l + 1) - (l + 1) * (l + 1)) / 2 <= s) l++;
            while (l > 0 && (769 * l - l * l) / 2 > s) l--;
            int off = (769 * l - l * l) / 2;
            g_L[s] = l;
            g_R[s] = l + 1 + (s - off);
        }
    }
}

// ---------------- gx GEMM: gx[dir] = x @ Wih^T + b   (NT layout) ----------------
// M=386, N=2048, K=512. A=[M,K] row-major, B=[N,K] row-major.
__global__ __launch_bounds__(256) void gx_gemm(const float* __restrict__ Wf,
                                               const float* __restrict__ bfv,
                                               const float* __restrict__ Wb,
                                               const float* __restrict__ bbv)
{
    int dir = blockIdx.z;
    const float* B    = dir ? Wb : Wf;
    const float* bias = dir ? bbv : bfv;
    const float* A = g_x;
    float* C = g_gx + (size_t)dir * kT * kG;

    int tid = threadIdx.x;
    int m0 = blockIdx.x * 64, n0 = blockIdx.y * 64;
    __shared__ __align__(16) float As[16][68];
    __shared__ __align__(16) float Bs[16][68];
    float acc[4][4] = {};
    int tx = tid & 15, ty = tid >> 4;

    for (int k0 = 0; k0 < kH; k0 += 16) {
        int mr = tid >> 2, kq = (tid & 3) * 4;
        int gm = m0 + mr;
        float4 va = (gm < kT) ? *(const float4*)&A[(size_t)gm * kH + k0 + kq]
                              : make_float4(0.f, 0.f, 0.f, 0.f);
        As[kq + 0][mr] = va.x; As[kq + 1][mr] = va.y;
        As[kq + 2][mr] = va.z; As[kq + 3][mr] = va.w;
        float4 vb = *(const float4*)&B[(size_t)(n0 + mr) * kH + k0 + kq];
        Bs[kq + 0][mr] = vb.x; Bs[kq + 1][mr] = vb.y;
        Bs[kq + 2][mr] = vb.z; Bs[kq + 3][mr] = vb.w;
        __syncthreads();
        #pragma unroll
        for (int k = 0; k < 16; k++) {
            float4 a = *(const float4*)&As[k][ty * 4];
            float4 bv = *(const float4*)&Bs[k][tx * 4];
            float av[4] = {a.x, a.y, a.z, a.w};
            float bw[4] = {bv.x, bv.y, bv.z, bv.w};
            #pragma unroll
            for (int i = 0; i < 4; i++)
                #pragma unroll
                for (int j = 0; j < 4; j++)
                    acc[i][j] = fmaf(av[i], bw[j], acc[i][j]);
        }
        __syncthreads();
    }
    #pragma unroll
    for (int i = 0; i < 4; i++) {
        int gm = m0 + ty * 4 + i;
        if (gm < kT) {
            #pragma unroll
            for (int j = 0; j < 4; j++) {
                int n = n0 + tx * 4 + j;
                C[(size_t)gm * kG + n] = acc[i][j] + bias[n];
            }
        }
    }
}

// ---------------- persistent bidirectional LSTM ----------------
// 64 CTAs: CTAs [0,32) = forward, [32,64) = backward. Each CTA owns 16 hidden
// units (64 gate rows); Whh slice lives in registers (16 float4 per thread).
// Per-direction release/acquire barrier on padded counters.
__global__ __launch_bounds__(512, 1) void lstm_kernel(const float* __restrict__ Wfhh,
                                                      const float* __restrict__ Wbhh)
{
    int tid = threadIdx.x;
    int dir = blockIdx.x >> 5;
    int cta = blockIdx.x & 31;
    int lr  = tid >> 3;      // local gate row 0..63
    int sl  = tid & 7;       // slice within row
    int gate = lr >> 4, u = lr & 15;
    int ug  = cta * 16 + u;
    int row = gate * kH + ug;

    const float* W = (dir ? Wbhh : Wfhh) + (size_t)row * kH;
    float4 w4[16];
    int koff[16];
    #pragma unroll
    for (int m = 0; m < 16; m++) {
        int ko = sl * 64 + ((4 * m + 4 * sl) & 63);   // bank-rotated k offset
        koff[m] = ko;
        w4[m] = *(const float4*)&W[ko];
    }

    __shared__ __align__(16) float sh_h[kH];
    __shared__ float sh_g[64];
    __shared__ float sh_c[16];
    if (tid < 16) sh_c[tid] = 0.f;

    float* hbase = g_h + (size_t)dir * kT * kH;
    const float* gxbase = g_gx + (size_t)dir * kT * kG;
    unsigned* bar = &g_bar[dir * 32];

    for (int step = 0; step < kT; step++) {
        int t = dir ? (kT - 1 - step) : step;

        // prefetch gx[t] early (independent of h, hides L2 latency under gemv)
        float4 gxv;
        if (tid < 16) {
            const float* gx = gxbase + (size_t)t * kG + cta * 16 + tid;
            gxv.x = __ldcg(gx);
            gxv.y = __ldcg(gx + kH);
            gxv.z = __ldcg(gx + 2 * kH);
            gxv.w = __ldcg(gx + 3 * kH);
        }

        if (step == 0) {
            sh_h[tid] = 0.f;
        } else {
            int tp = dir ? t + 1 : t - 1;
            sh_h[tid] = __ldcg(&hbase[(size_t)tp * kH + tid]);
        }
        __syncthreads();

        float acc = 0.f;
        #pragma unroll
        for (int m = 0; m < 16; m++) {
            float4 h4 = *(const float4*)&sh_h[koff[m]];
            acc = fmaf(w4[m].x, h4.x, acc);
            acc = fmaf(w4[m].y, h4.y, acc);
            acc = fmaf(w4[m].z, h4.z, acc);
            acc = fmaf(w4[m].w, h4.w, acc);
        }
        acc += __shfl_down_sync(0xffffffffu, acc, 4, 8);
        acc += __shfl_down_sync(0xffffffffu, acc, 2, 8);
        acc += __shfl_down_sync(0xffffffffu, acc, 1, 8);
        if (sl == 0) sh_g[lr] = acc;
        __syncthreads();

        if (tid < 16) {
            float gi = gxv.x + sh_g[tid];
            float gf = gxv.y + sh_g[16 + tid];
            float gg = gxv.z + sh_g[32 + tid];
            float go = gxv.w + sh_g[48 + tid];
            float si = fsig(gi);
            float sf = fsig(gf);
            float so = fsig(go);
            float c = sf * sh_c[tid] + si * ftanh(gg);
            sh_c[tid] = c;
            float h = so * ftanh(c);
            __stcg(&hbase[(size_t)t * kH + cta * 16 + tid], h);
        }
        __syncthreads();

        if (step < kT - 1) {
            if (tid == 0) {
                // release arrive (orders prior CTA writes via the preceding bar.sync)
                asm volatile("red.release.gpu.add.u32 [%0], %1;"
                             :: "l"(bar), "r"(1u) : "memory");
                unsigned tgt = (unsigned)(step + 1) * 32u;
                unsigned v;
                do {
                    asm volatile("ld.acquire.gpu.u32 %0, [%1];"
                                 : "=r"(v) : "l"(bar) : "memory");
                } while (v < tgt);
            }
            __syncthreads();
        }
    }
}

// ---------------- A-table GEMMs: A[dir] = h[dir] @ Wtab[dir_half]  (NN) --------
// M=386, N=1024, K=512. B=[K,N] row-major (n contiguous).
__global__ __launch_bounds__(256) void pre_gemm(const float* __restrict__ W1,
                                                const float* __restrict__ V1)
{
    int dir = blockIdx.z & 1, tab = blockIdx.z >> 1;
    const float* A = g_h + (size_t)dir * kT * kH;
    const float* B = (tab ? V1 : W1) + (size_t)dir * kH * kE;
    float* C = (tab ? g_Av : g_A1) + (size_t)dir * kT * kE;

    int tid = threadIdx.x;
    int m0 = blockIdx.x * 64, n0 = blockIdx.y * 64;
    __shared__ __align__(16) float As[16][68];
    __shared__ __align__(16) float Bs[16][68];
    float acc[4][4] = {};
    int tx = tid & 15, ty = tid >> 4;

    for (int k0 = 0; k0 < kH; k0 += 16) {
        {
            int mr = tid >> 2, kq = (tid & 3) * 4;
            int gm = m0 + mr;
            float4 va = (gm < kT) ? *(const float4*)&A[(size_t)gm * kH + k0 + kq]
                                  : make_float4(0.f, 0.f, 0.f, 0.f);
            As[kq + 0][mr] = va.x; As[kq + 1][mr] = va.y;
            As[kq + 2][mr] = va.z; As[kq + 3][mr] = va.w;
        }
        {
            int kr = tid >> 4, nq = (tid & 15) * 4;
            float4 vb = *(const float4*)&B[(size_t)(k0 + kr) * kE + n0 + nq];
            *(float4*)&Bs[kr][nq] = vb;
        }
        __syncthreads();
        #pragma unroll
        for (int k = 0; k < 16; k++) {
            float4 a = *(const float4*)&As[k][ty * 4];
            float4 bv = *(const float4*)&Bs[k][tx * 4];
            float av[4] = {a.x, a.y, a.z, a.w};
            float bw[4] = {bv.x, bv.y, bv.z, bv.w};
            #pragma unroll
            for (int i = 0; i < 4; i++)
                #pragma unroll
                for (int j = 0; j < 4; j++)
                    acc[i][j] = fmaf(av[i], bw[j], acc[i][j]);
        }
        __syncthreads();
    }
    #pragma unroll
    for (int i = 0; i < 4; i++) {
        int gm = m0 + ty * 4 + i;
        if (gm < kT) {
            #pragma unroll
            for (int j = 0; j < 4; j++)
                C[(size_t)gm * kE + n0 + tx * 4 + j] = acc[i][j];
        }
    }
}

// ---------------- fused span kernel (software-pipelined, dynamic smem) ---------
// Tile: 64 spans x 128 labels, K=1024 in chunks of 32. Double-buffered h1/W2:
// build of chunk kc+1 (global loads) overlaps FMA GEMM of chunk kc; one
// __syncthreads per chunk.
#define BUILD_CHUNK(kc_, p_) do {                                              \
    int k0_ = (kc_) * 32;                                                      \
    _Pragma("unroll")                                                          \
    for (int i_ = 0; i_ < 4; i_++) {                                           \
        int e_ = tid + 256 * i_;                                               \
        int kk_ = e_ >> 5, nq_ = (e_ & 31) * 4;                                \
        *(float4*)&w2s[p_][kk_][nq_] =                                         \
            *(const float4*)&W2[(size_t)(k0_ + kk_) * 128 + nq_];              \
    }                                                                          \
    int kg_ = k0_ + lane_k;                                                    \
    float b1v_ = b1[kg_], c1v_ = c1[kg_], v2v_ = V2[kg_];                      \
    _Pragma("unroll")                                                          \
    for (int i_ = 0; i_ < 8; i_++) {                                           \
        int m_ = mwarp + 8 * i_;                                               \
        int l_ = sL[m_], r_ = sR[m_];                                          \
        size_t rr_ = (size_t)r_ * kE + kg_, ll_ = (size_t)l_ * kE + kg_;       \
        size_t l1_ = (size_t)(l_ + 1) * kE + kg_;                              \
        size_t r1_ = (size_t)(r_ + 1) * kE + kg_;                              \
        float hl_ = A1f[rr_] - A1f[ll_] + A1b[l1_] - A1b[r1_] + b1v_;          \
        h1s[p_][m_][lane_k] = fmaxf(hl_, 0.f);                                 \
        float hv_ = Avf[rr_] - Avf[ll_] + Avb[l1_] - Avb[r1_] + c1v_;          \
        spl[i_] = fmaf(fmaxf(hv_, 0.f), v2v_, spl[i_]);                        \
    }                                                                          \
} while (0)

constexpr int kSpanSmem = (2 * 64 * 33 + 2 * 32 * 128) * 4;   // 49664 bytes

__global__ __launch_bounds__(256) void span_kernel(const float* __restrict__ W2,
                                                   const float* __restrict__ b1,
                                                   const float* __restrict__ b2,
                                                   const float* __restrict__ V2,
                                                   const float* __restrict__ c1,
                                                   const float* __restrict__ c2,
                                                   float* __restrict__ out)
{
    extern __shared__ __align__(16) float dyn[];
    float (*h1s)[64][33]  = (float (*)[64][33])dyn;               // 2 buffers
    float (*w2s)[32][128] = (float (*)[32][128])(dyn + 2 * 64 * 33);
    __shared__ int sL[64], sR[64];
    __shared__ float ssplit[64];

    int tid = threadIdx.x;
    int s0 = blockIdx.x * 64;
    if (tid < 64) {
        int s = s0 + tid;
        if (s < kS) { sL[tid] = g_L[s]; sR[tid] = g_R[s]; }
        else        { sL[tid] = 0;      sR[tid] = 1;      }
        ssplit[tid] = 0.f;
    }
    __syncthreads();

    const float* A1f = g_A1;
    const float* A1b = g_A1 + (size_t)kT * kE;
    const float* Avf = g_Av;
    const float* Avb = g_Av + (size_t)kT * kE;

    float acc[4][8] = {};
    float spl[8] = {};
    int lane_k = tid & 31;
    int mwarp  = tid >> 5;
    int tx = tid & 15, ty = tid >> 4;

    BUILD_CHUNK(0, 0);
    __syncthreads();

    for (int kc = 0; kc < 32; kc++) {
        int p = kc & 1;
        if (kc < 31) BUILD_CHUNK(kc + 1, p ^ 1);
        // GEMM: 64x128 += h1(64x32) * w2(32x128) from buffer p
        #pragma unroll
        for (int k = 0; k < 32; k++) {
            float4 wA = *(const float4*)&w2s[p][k][tx * 8];
            float4 wB = *(const float4*)&w2s[p][k][tx * 8 + 4];
            #pragma unroll
            for (int i = 0; i < 4; i++) {
                float a = h1s[p][ty * 4 + i][k];
                acc[i][0] = fmaf(a, wA.x, acc[i][0]);
                acc[i][1] = fmaf(a, wA.y, acc[i][1]);
                acc[i][2] = fmaf(a, wA.z, acc[i][2]);
                acc[i][3] = fmaf(a, wA.w, acc[i][3]);
                acc[i][4] = fmaf(a, wB.x, acc[i][4]);
                acc[i][5] = fmaf(a, wB.y, acc[i][5]);
                acc[i][6] = fmaf(a, wB.z, acc[i][6]);
                acc[i][7] = fmaf(a, wB.w, acc[i][7]);
            }
        }
        __syncthreads();
    }

    // reduce split partials (each warp owns spans m with m%8 == warp id)
    #pragma unroll
    for (int i = 0; i < 8; i++) {
        float v = spl[i];
        v += __shfl_down_sync(0xffffffffu, v, 16);
        v += __shfl_down_sync(0xffffffffu, v, 8);
        v += __shfl_down_sync(0xffffffffu, v, 4);
        v += __shfl_down_sync(0xffffffffu, v, 2);
        v += __shfl_down_sync(0xffffffffu, v, 1);
        if (lane_k == 0) ssplit[mwarp + 8 * i] = v;
    }
    __syncthreads();

    float c2v = c2[0];
    #pragma unroll
    for (int i = 0; i < 4; i++) {
        int s = s0 + ty * 4 + i;
        if (s < kS) {
            float* po = out + (size_t)s * 129;
            #pragma unroll
            for (int j = 0; j < 8; j++) {
                int n = tx * 8 + j;
                po[n] = acc[i][j] + b2[n];
            }
            if (tx == 0) po[128] = ssplit[ty * 4 + i] + c2v;
        }
    }
}

// ---------------- launch ----------------
extern "C" void kernel_launch(void* const* d_in, const int* in_sizes, int n_in,
                              void* d_out, int out_size)
{
    const int*   tag_ids  = (const int*)  d_in[0];
    const int*   word_ids = (const int*)  d_in[1];
    const float* tag_emb  = (const float*)d_in[2];
    const float* word_emb = (const float*)d_in[3];
    const float* Wf_ih    = (const float*)d_in[4];
    const float* Wf_hh    = (const float*)d_in[5];
    const float* bf       = (const float*)d_in[6];
    const float* Wb_ih    = (const float*)d_in[7];
    const float* Wb_hh    = (const float*)d_in[8];
    const float* bb       = (const float*)d_in[9];
    const float* W1       = (const float*)d_in[10];
    const float* b1       = (const float*)d_in[11];
    const float* W2       = (const float*)d_in[12];
    const float* b2       = (const float*)d_in[13];
    const float* V1       = (const float*)d_in[14];
    const float* c1       = (const float*)d_in[15];
    const float* V2       = (const float*)d_in[16];
    const float* c2       = (const float*)d_in[17];
    float* out = (float*)d_out;

    cudaFuncSetAttribute(span_kernel, cudaFuncAttributeMaxDynamicSharedMemorySize,
                         kSpanSmem);

    init_kernel<<<kT + (kS + 255) / 256, 256>>>(tag_ids, word_ids, tag_emb, word_emb);
    gx_gemm<<<dim3((kT + 63) / 64, kG / 64, 2), 256>>>(Wf_ih, bf, Wb_ih, bb);
    lstm_kernel<<<64, 512>>>(Wf_hh, Wb_hh);
    pre_gemm<<<dim3((kT + 63) / 64, kE / 64, 4), 256>>>(W1, V1);
    span_kernel<<<(kS + 63) / 64, 256, kSpanSmem>>>(W2, b1, b2, V2, c1, c2, out);
}